// round 7
// baseline (speedup 1.0000x reference)
#include <cuda_runtime.h>

#define SS 512
#define NUNITS 9
#define DSTRIDE 520   // 512 data + 8 zero pad; 130 float4 per row
#define MAXB 128
#define BPER 15       // batches per block slice; smem = 15*520*4 = 31.2 KB

__device__ float g_diag[MAXB * DSTRIDE];
__device__ float g_bias[SS * SS];

// Fused prep: diag gather (MLP=4 per thread) on low blocks, bias reduction
// streaming behind it.
__global__ void prep_kernel(const float* __restrict__ in,
                            const float* __restrict__ bb,
                            int B, int ndiag_blocks) {
    if (blockIdx.x < (unsigned)ndiag_blocks) {
        int idx = blockIdx.x * blockDim.x + threadIdx.x;
        int bq = idx / DSTRIDE;
        int j  = idx - bq * DSTRIDE;
        int b4 = bq * 4;
        if (b4 >= B) return;
        float v[4] = {0.f, 0.f, 0.f, 0.f};
        bool jin = (j < SS);
#pragma unroll
        for (int k = 0; k < 4; k++) {
            if (jin && b4 + k < B)
                v[k] = __ldg(in + (size_t)(b4 + k) * SS * SS + (size_t)j * (SS + 1));
        }
#pragma unroll
        for (int k = 0; k < 4; k++) {
            if (b4 + k < B) g_diag[(size_t)(b4 + k) * DSTRIDE + j] = v[k];
        }
    } else {
        int t4 = (blockIdx.x - ndiag_blocks) * blockDim.x + threadIdx.x;
        if (t4 >= (SS * SS) / 4) return;
        const float4* bp = (const float4*)(bb + (size_t)t4 * 36);
        float v[36];
#pragma unroll
        for (int k = 0; k < 9; k++) {
            float4 q = bp[k];
            v[k * 4 + 0] = q.x; v[k * 4 + 1] = q.y;
            v[k * 4 + 2] = q.z; v[k * 4 + 3] = q.w;
        }
        float4 s;
        float* sp = (float*)&s;
#pragma unroll
        for (int jj = 0; jj < 4; jj++) {
            float acc = 0.0f;
#pragma unroll
            for (int t = 0; t < 9; t++) acc += v[jj * 9 + t];
            sp[jj] = acc;
        }
        *(float4*)(g_bias + (size_t)t4 * 4) = s;
    }
}

// Main kernel: block = (i-row, batch slice of BPER). The slice's diag rows
// (contiguous in g_diag) are staged into smem ONCE; the batch loop then runs
// entirely on fixed-latency LDS hits + FMA + streaming stores. No per-iter
// L2 reads, no per-iter barriers.
__global__ __launch_bounds__(128, 6)
void cnn_kernel(const float* __restrict__ w,
                float* __restrict__ out,
                int B) {
    __shared__ float sdiag[BPER * DSTRIDE];

    int i   = blockIdx.x;          // 0..511
    int tid = threadIdx.x;
    int j0  = tid << 2;            // 0,4,...,508
    int b0  = blockIdx.y * BPER;
    int b1  = b0 + BPER;
    if (b1 > B) b1 = B;
    int nb  = b1 - b0;

    // ---- stage slice: contiguous copy g_diag[b0*DSTRIDE ..] -> smem ----
    {
        const float4* g4 = (const float4*)(g_diag + (size_t)b0 * DSTRIDE);
        float4* s4 = (float4*)sdiag;
        int nf4 = nb * (DSTRIDE / 4);          // <= 1950
        for (int k = tid; k < nf4; k += 128)
            s4[k] = g4[k];
    }

    // ---- weights + bias prologue (overlaps the staging loads) ----
    float wv[36];
    const float4* wp4 = (const float4*)(w + ((size_t)i * SS + j0) * NUNITS);
#pragma unroll
    for (int k = 0; k < 9; k++) {
        float4 q = wp4[k];
        wv[k * 4 + 0] = q.x; wv[k * 4 + 1] = q.y;
        wv[k * 4 + 2] = q.z; wv[k * 4 + 3] = q.w;
    }
#pragma unroll
    for (int n = 0; n < 36; n++) {
        int t = n % 9;                          // compile-time per n
        wv[n] *= (i + (t / 3) < SS) ? 9.0f : 0.0f;
    }
    float4 bias4 = *(const float4*)(g_bias + (size_t)i * SS + j0);

    __syncthreads();

    // ---- batch loop: 3x LDS.128 + 36 FMA + 1x STG.128 (streaming) ----
    float* op = out + (size_t)b0 * (SS * SS) + (size_t)i * SS + j0;
    const float* srow = sdiag + j0;

    for (int lb = 0; lb < nb; ++lb) {
        const float4* sp = (const float4*)srow;
        float4 c0 = sp[0], c1 = sp[1], c2 = sp[2];
        float d[12] = {c0.x, c0.y, c0.z, c0.w,
                       c1.x, c1.y, c1.z, c1.w,
                       c2.x, c2.y, c2.z, c2.w};

        float s0 = bias4.x, s1 = bias4.y, s2 = bias4.z, s3 = bias4.w;
#pragma unroll
        for (int t = 0; t < 9; t++) {
            s0 = fmaf(d[t],     wv[t],      s0);
            s1 = fmaf(d[t + 1], wv[9 + t],  s1);
            s2 = fmaf(d[t + 2], wv[18 + t], s2);
            s3 = fmaf(d[t + 3], wv[27 + t], s3);
        }
        float4 o; o.x = s0; o.y = s1; o.z = s2; o.w = s3;
        __stcs((float4*)op, o);                 // write-once: evict-first
        op += SS * SS;
        srow += DSTRIDE;
    }
}

extern "C" void kernel_launch(void* const* d_in, const int* in_sizes, int n_in,
                              void* d_out, int out_size) {
    const float* in = (const float*)d_in[0];   // inputs (B,512,512,1) f32
    const float* w  = (const float*)d_in[1];   // w (512*512*9,) f32
    const float* bb = (const float*)d_in[2];   // b (512*512*9,) f32
    float* out = (float*)d_out;                // (B, 512*512) f32

    int B = in_sizes[0] / (SS * SS);
    if (B > MAXB) B = MAXB;

    {
        int bq = (B + 3) / 4;
        int ndiag_blocks = (bq * DSTRIDE + 255) / 256;          // ~53
        int nbias_blocks = ((SS * SS) / 4 + 255) / 256;         // 256
        prep_kernel<<<ndiag_blocks + nbias_blocks, 256>>>(in, bb, B, ndiag_blocks);
    }

    int nslice = (B + BPER - 1) / BPER;        // 7 for B=100
    dim3 grid(SS, nslice);                     // 3584 blocks
    cnn_kernel<<<grid, 128>>>(w, out, B);
}